// round 15
// baseline (speedup 1.0000x reference)
#include <cuda_runtime.h>
#include <cuda_bf16.h>
#include <mma.h>
#include <math.h>

using namespace nvcuda;

// Problem dims
#define Bsz 8
#define Lsz 128
#define Hsz 512
#define Vsz 32000
#define NROWS (Bsz * Lsz)        // 1024
#define PROB_ELEMS ((long)NROWS * Vsz)   // 32768000

// ---------------- scratch (single __device__ global, offsets in floats) ---
// EA = [1024 rows][1024 cols]: cols 0-511 = embedded, cols 512-1023 = attn_applied
#define OFF_EA       0
#define OFF_SATTN    (OFF_EA + NROWS * 1024)
#define OFF_X        (OFF_SATTN + NROWS * Lsz)
#define OFF_GI       (OFF_X + NROWS * Hsz)
#define OFF_GRUOUT   (OFF_GI + NROWS * 3 * Hsz)
#define OFF_CTX      (OFF_GRUOUT + NROWS * Hsz)
#define OFF_MIX      (OFF_CTX + Bsz * Hsz)
#define OFF_HGLOB    (OFF_MIX + NROWS)
#define OFF_BAR      (OFF_HGLOB + 2 * Bsz * Hsz)
#define SCRATCH_TOTAL (OFF_BAR + 64)

__device__ float d_scratch[SCRATCH_TOTAL];

// bf16 hi/lo split buffers for the big GEMM
__device__ __nv_bfloat16 d_Bhi[(long)Vsz * Hsz];
__device__ __nv_bfloat16 d_Blo[(long)Vsz * Hsz];
__device__ __nv_bfloat16 d_Ahi[NROWS * Hsz];
__device__ __nv_bfloat16 d_Alo[NROWS * Hsz];

// ---------------- embedding gather (into EA cols 0-511) -------------------
__global__ void gather_kernel(const int* __restrict__ toks,
                              const float* __restrict__ emb,
                              float* __restrict__ ea) {
    int row = blockIdx.x;
    int tok = toks[row];
    const float4* s = (const float4*)(emb + (long)tok * Hsz);
    float4* d = (float4*)(ea + (long)row * 1024);
    d[threadIdx.x] = s[threadIdx.x];
}

// ---------------- fp32 -> bf16 hi/lo split --------------------------------
__global__ void split_bf16_kernel(const float* __restrict__ src,
                                  __nv_bfloat16* __restrict__ hi,
                                  __nv_bfloat16* __restrict__ lo, int n4) {
    int i = blockIdx.x * blockDim.x + threadIdx.x;
    if (i >= n4) return;
    float4 x = ((const float4*)src)[i];
    __nv_bfloat16 h0 = __float2bfloat16(x.x);
    __nv_bfloat16 h1 = __float2bfloat16(x.y);
    __nv_bfloat16 h2 = __float2bfloat16(x.z);
    __nv_bfloat16 h3 = __float2bfloat16(x.w);
    __nv_bfloat16 l0 = __float2bfloat16(x.x - __bfloat162float(h0));
    __nv_bfloat16 l1 = __float2bfloat16(x.y - __bfloat162float(h1));
    __nv_bfloat16 l2 = __float2bfloat16(x.z - __bfloat162float(h2));
    __nv_bfloat16 l3 = __float2bfloat16(x.w - __bfloat162float(h3));
    __nv_bfloat162 ha, hb, la, lb;
    ha.x = h0; ha.y = h1; hb.x = h2; hb.y = h3;
    la.x = l0; la.y = l1; lb.x = l2; lb.y = l3;
    ((__nv_bfloat162*)hi)[2 * i]     = ha;
    ((__nv_bfloat162*)hi)[2 * i + 1] = hb;
    ((__nv_bfloat162*)lo)[2 * i]     = la;
    ((__nv_bfloat162*)lo)[2 * i + 1] = lb;
}

// ---------------- bf16 split-precision WMMA GEMM --------------------------
#define TSTRIDE 40
#define MMA_SMEM (4 * 2 * 128 * TSTRIDE * 2)   // 81920 bytes

__global__ __launch_bounds__(256)
void mma_out_gemm(const __nv_bfloat16* __restrict__ gAhi,
                  const __nv_bfloat16* __restrict__ gAlo,
                  const __nv_bfloat16* __restrict__ gBhi,
                  const __nv_bfloat16* __restrict__ gBlo,
                  float* __restrict__ C) {
    extern __shared__ __nv_bfloat16 smb[];
    const int SEG = 128 * TSTRIDE;
    const int tid = threadIdx.x;
    const int warp = tid >> 5;
    const long bm = (long)blockIdx.x * 128;
    const long bn = (long)blockIdx.y * 128;
    const int wm = (warp & 1) * 64;
    const int wn = (warp >> 1) * 32;

    wmma::fragment<wmma::accumulator, 16, 16, 16, float> acc[4][2];
    #pragma unroll
    for (int mi = 0; mi < 4; mi++)
        #pragma unroll
        for (int ni = 0; ni < 2; ni++)
            wmma::fill_fragment(acc[mi][ni], 0.0f);

    const int r0 = tid >> 2, k80 = (tid & 3) * 8;
    const int r1 = (tid + 256) >> 2, k81 = ((tid + 256) & 3) * 8;

    const __nv_bfloat16* gsrc[4];
    gsrc[0] = gAhi + bm * Hsz;
    gsrc[1] = gAlo + bm * Hsz;
    gsrc[2] = gBhi + bn * Hsz;
    gsrc[3] = gBlo + bn * Hsz;

    uint4 pf[4][2];
    const int NT = Hsz / 32;

    #pragma unroll
    for (int a = 0; a < 4; a++) {
        pf[a][0] = *(const uint4*)(gsrc[a] + (long)r0 * Hsz + k80);
        pf[a][1] = *(const uint4*)(gsrc[a] + (long)r1 * Hsz + k81);
    }
    #pragma unroll
    for (int a = 0; a < 4; a++) {
        *(uint4*)(smb + a * SEG + r0 * TSTRIDE + k80) = pf[a][0];
        *(uint4*)(smb + a * SEG + r1 * TSTRIDE + k81) = pf[a][1];
    }
    __syncthreads();

    for (int t = 0; t < NT; t++) {
        const int buf = t & 1;
        const bool more = (t + 1 < NT);
        if (more) {
            const int kt = (t + 1) * 32;
            #pragma unroll
            for (int a = 0; a < 4; a++) {
                pf[a][0] = *(const uint4*)(gsrc[a] + (long)r0 * Hsz + kt + k80);
                pf[a][1] = *(const uint4*)(gsrc[a] + (long)r1 * Hsz + kt + k81);
            }
        }

        const __nv_bfloat16* sAh = smb + buf * 4 * SEG + 0 * SEG;
        const __nv_bfloat16* sAl = smb + buf * 4 * SEG + 1 * SEG;
        const __nv_bfloat16* sBh = smb + buf * 4 * SEG + 2 * SEG;
        const __nv_bfloat16* sBl = smb + buf * 4 * SEG + 3 * SEG;

        #pragma unroll
        for (int ks = 0; ks < 32; ks += 16) {
            wmma::fragment<wmma::matrix_b, 16, 16, 16, __nv_bfloat16, wmma::col_major> fbh[2], fbl[2];
            #pragma unroll
            for (int ni = 0; ni < 2; ni++) {
                wmma::load_matrix_sync(fbh[ni], sBh + (wn + ni * 16) * TSTRIDE + ks, TSTRIDE);
                wmma::load_matrix_sync(fbl[ni], sBl + (wn + ni * 16) * TSTRIDE + ks, TSTRIDE);
            }
            #pragma unroll
            for (int mi = 0; mi < 4; mi++) {
                wmma::fragment<wmma::matrix_a, 16, 16, 16, __nv_bfloat16, wmma::row_major> fah, fal;
                wmma::load_matrix_sync(fah, sAh + (wm + mi * 16) * TSTRIDE + ks, TSTRIDE);
                wmma::load_matrix_sync(fal, sAl + (wm + mi * 16) * TSTRIDE + ks, TSTRIDE);
                #pragma unroll
                for (int ni = 0; ni < 2; ni++) {
                    wmma::mma_sync(acc[mi][ni], fah, fbh[ni], acc[mi][ni]);
                    wmma::mma_sync(acc[mi][ni], fah, fbl[ni], acc[mi][ni]);
                    wmma::mma_sync(acc[mi][ni], fal, fbh[ni], acc[mi][ni]);
                }
            }
        }

        if (more) {
            const int nb = buf ^ 1;
            #pragma unroll
            for (int a = 0; a < 4; a++) {
                *(uint4*)(smb + nb * 4 * SEG + a * SEG + r0 * TSTRIDE + k80) = pf[a][0];
                *(uint4*)(smb + nb * 4 * SEG + a * SEG + r1 * TSTRIDE + k81) = pf[a][1];
            }
        }
        __syncthreads();
    }

    #pragma unroll
    for (int mi = 0; mi < 4; mi++)
        #pragma unroll
        for (int ni = 0; ni < 2; ni++) {
            long m = bm + wm + mi * 16;
            long n = bn + wn + ni * 16;
            wmma::store_matrix_sync(C + m * Vsz + n, acc[mi][ni], Vsz, wmma::mem_row_major);
        }
}

// ---------------- SGEMM 128x128x16 for the small GEMMs --------------------
#define FLAG_ACCUM 1
#define FLAG_BIAS  2
#define FLAG_RELU  4
#define BM 128
#define BN 128
#define BK 16
#define SPAD 4

__global__ __launch_bounds__(256)
void sgemm128_kernel(const float* __restrict__ A, int lda,
                     const float* __restrict__ B, int ldb,
                     float* __restrict__ C, int ldc,
                     int K, const float* __restrict__ bias, int flags) {
    __shared__ float As[2][BK][BM + SPAD];
    __shared__ float Bs[2][BK][BN + SPAD];

    const int tid = threadIdx.x;
    const int tx = tid & 15;
    const int ty = tid >> 4;
    const long bm = (long)blockIdx.y * BM;
    const long bn = (long)blockIdx.x * BN;

    const int r0 = tid >> 2;
    const int r1 = r0 + 64;
    const int kq = (tid & 3) << 2;

    const float* Ag = A + (bm + r0) * lda + kq;
    const float* Ag2 = A + (bm + r1) * lda + kq;
    const float* Bg = B + (bn + r0) * ldb + kq;
    const float* Bg2 = B + (bn + r1) * ldb + kq;

    float acc[8][8];
    #pragma unroll
    for (int i = 0; i < 8; i++)
        #pragma unroll
        for (int j = 0; j < 8; j++) acc[i][j] = 0.0f;

    {
        float4 a0 = *(const float4*)(Ag);
        float4 a1 = *(const float4*)(Ag2);
        float4 b0 = *(const float4*)(Bg);
        float4 b1 = *(const float4*)(Bg2);
        As[0][kq + 0][r0] = a0.x; As[0][kq + 1][r0] = a0.y;
        As[0][kq + 2][r0] = a0.z; As[0][kq + 3][r0] = a0.w;
        As[0][kq + 0][r1] = a1.x; As[0][kq + 1][r1] = a1.y;
        As[0][kq + 2][r1] = a1.z; As[0][kq + 3][r1] = a1.w;
        Bs[0][kq + 0][r0] = b0.x; Bs[0][kq + 1][r0] = b0.y;
        Bs[0][kq + 2][r0] = b0.z; Bs[0][kq + 3][r0] = b0.w;
        Bs[0][kq + 0][r1] = b1.x; Bs[0][kq + 1][r1] = b1.y;
        Bs[0][kq + 2][r1] = b1.z; Bs[0][kq + 3][r1] = b1.w;
    }
    __syncthreads();

    int buf = 0;
    const int T = K / BK;
    for (int t = 0; t < T; t++) {
        float4 a0, a1, b0, b1;
        const bool more = (t + 1 < T);
        if (more) {
            int kt = (t + 1) * BK;
            a0 = *(const float4*)(Ag + kt);
            a1 = *(const float4*)(Ag2 + kt);
            b0 = *(const float4*)(Bg + kt);
            b1 = *(const float4*)(Bg2 + kt);
        }
        #pragma unroll
        for (int k = 0; k < BK; k++) {
            float4 af0 = *(const float4*)&As[buf][k][ty * 8];
            float4 af1 = *(const float4*)&As[buf][k][ty * 8 + 4];
            float4 bf0 = *(const float4*)&Bs[buf][k][tx * 8];
            float4 bf1 = *(const float4*)&Bs[buf][k][tx * 8 + 4];
            float ar[8] = {af0.x, af0.y, af0.z, af0.w, af1.x, af1.y, af1.z, af1.w};
            float br[8] = {bf0.x, bf0.y, bf0.z, bf0.w, bf1.x, bf1.y, bf1.z, bf1.w};
            #pragma unroll
            for (int i = 0; i < 8; i++)
                #pragma unroll
                for (int j = 0; j < 8; j++)
                    acc[i][j] += ar[i] * br[j];
        }
        if (more) {
            int nb = buf ^ 1;
            As[nb][kq + 0][r0] = a0.x; As[nb][kq + 1][r0] = a0.y;
            As[nb][kq + 2][r0] = a0.z; As[nb][kq + 3][r0] = a0.w;
            As[nb][kq + 0][r1] = a1.x; As[nb][kq + 1][r1] = a1.y;
            As[nb][kq + 2][r1] = a1.z; As[nb][kq + 3][r1] = a1.w;
            Bs[nb][kq + 0][r0] = b0.x; Bs[nb][kq + 1][r0] = b0.y;
            Bs[nb][kq + 2][r0] = b0.z; Bs[nb][kq + 3][r0] = b0.w;
            Bs[nb][kq + 0][r1] = b1.x; Bs[nb][kq + 1][r1] = b1.y;
            Bs[nb][kq + 2][r1] = b1.z; Bs[nb][kq + 3][r1] = b1.w;
        }
        __syncthreads();
        buf ^= 1;
    }

    #pragma unroll
    for (int i = 0; i < 8; i++) {
        long m = bm + ty * 8 + i;
        long n = bn + tx * 8;
        float* cp = C + m * ldc + n;
        float v[8];
        #pragma unroll
        for (int j = 0; j < 8; j++) v[j] = acc[i][j];
        if (flags & FLAG_ACCUM) {
            float4 cc0 = *(float4*)(cp);
            float4 cc1 = *(float4*)(cp + 4);
            v[0]+=cc0.x; v[1]+=cc0.y; v[2]+=cc0.z; v[3]+=cc0.w;
            v[4]+=cc1.x; v[5]+=cc1.y; v[6]+=cc1.z; v[7]+=cc1.w;
        }
        if (flags & FLAG_BIAS) {
            float4 bb0 = *(const float4*)(bias + n);
            float4 bb1 = *(const float4*)(bias + n + 4);
            v[0]+=bb0.x; v[1]+=bb0.y; v[2]+=bb0.z; v[3]+=bb0.w;
            v[4]+=bb1.x; v[5]+=bb1.y; v[6]+=bb1.z; v[7]+=bb1.w;
        }
        if (flags & FLAG_RELU) {
            #pragma unroll
            for (int j = 0; j < 8; j++) v[j] = fmaxf(v[j], 0.0f);
        }
        *(float4*)(cp)     = make_float4(v[0], v[1], v[2], v[3]);
        *(float4*)(cp + 4) = make_float4(v[4], v[5], v[6], v[7]);
    }
}

// ---------------- attention softmax over axis=1 (over i, per (b,j)) ------
__global__ void attn_softmax_kernel(const float* __restrict__ S,
                                    float* __restrict__ W) {
    int b = blockIdx.x;
    int j = threadIdx.x;
    const float* p = S + (long)b * Lsz * Lsz + j;
    float m = -1e30f;
    for (int i = 0; i < Lsz; i++) m = fmaxf(m, p[i * Lsz]);
    float s = 0.0f;
    for (int i = 0; i < Lsz; i++) s += expf(p[i * Lsz] - m);
    float inv = 1.0f / s;
    float* w = W + (long)b * Lsz * Lsz + j;
    for (int i = 0; i < Lsz; i++) w[i * Lsz] = expf(p[i * Lsz] - m) * inv;
}

// ---------------- attn_applied -> EA cols 512-1023 ------------------------
__global__ void attn_applied_kernel(const float* __restrict__ attnw,
                                    const float* __restrict__ enc_out,
                                    float* __restrict__ ea) {
    int row = blockIdx.x;
    int b = row >> 7;
    __shared__ float w[Lsz];
    int tid = threadIdx.x;
    w[tid] = attnw[(long)row * Lsz + tid];
    __syncthreads();
    float a0 = 0, a1 = 0, a2 = 0, a3 = 0;
    const float* E = enc_out + (long)b * Lsz * Hsz;
    for (int j = 0; j < Lsz; j++) {
        float a = w[j];
        const float* er = E + j * Hsz;
        a0 += a * er[tid];       a1 += a * er[tid + 128];
        a2 += a * er[tid + 256]; a3 += a * er[tid + 384];
    }
    float* o = ea + (long)row * 1024 + 512;
    o[tid] = a0; o[tid + 128] = a1; o[tid + 256] = a2; o[tid + 384] = a3;
}

// ---------------- GRU: register-weight persistent kernel ------------------
// Barrier v2: arrivals on a counter, pollers spin on a RELEASE word that the
// last arriver writes once per step (no invalidation storm on the polled line).
#define GRU_BLOCKS 64
#define GRU_THREADS 128

__global__ void reset_bar_kernel(unsigned* bar) { bar[0] = 0u; bar[32] = 0u; }

__global__ void gru_kernel(const float* __restrict__ Whh,
                           const float* __restrict__ bhh,
                           const float* __restrict__ gi,
                           const float* __restrict__ h0,
                           float* __restrict__ out,
                           float* __restrict__ hglob,
                           unsigned* __restrict__ bar) {
    unsigned* counter = bar;
    unsigned* release = bar + 32;     // 128 B away: separate L2 line

    const int blk = blockIdx.x;
    const int tid = threadIdx.x;
    const int kc = tid & 15;
    const int jl = tid >> 4;
    const int j = (blk << 3) + jl;
    const bool owner = (kc == 0);

    // load weights into registers (96 floats)
    float4 wr[8], wz[8], wn[8];
    {
        const float4* Wr = (const float4*)(Whh + (long)j * Hsz + kc * 32);
        const float4* Wz = (const float4*)(Whh + (long)(Hsz + j) * Hsz + kc * 32);
        const float4* Wn = (const float4*)(Whh + (long)(2 * Hsz + j) * Hsz + kc * 32);
        #pragma unroll
        for (int i = 0; i < 8; i++) { wr[i] = Wr[i]; wz[i] = Wz[i]; wn[i] = Wn[i]; }
    }

    float bhr = 0, bhz = 0, bhn = 0;
    float holdr[8];
    float gir[8], giz[8], gin[8];
    if (owner) {
        bhr = bhh[j]; bhz = bhh[Hsz + j]; bhn = bhh[2 * Hsz + j];
        #pragma unroll
        for (int b = 0; b < 8; b++) {
            holdr[b] = h0[b * Hsz + j];
            long g = (long)(b << 7) * (3 * Hsz);   // t = 0
            gir[b] = gi[g + j];
            giz[b] = gi[g + Hsz + j];
            gin[b] = gi[g + 2 * Hsz + j];
        }
    }

    for (int t = 0; t < Lsz; t++) {
        const float* hsrc = (t == 0) ? h0 : (hglob + (t & 1) * (Bsz * Hsz));
        float ar[8], az[8], an[8];
        #pragma unroll
        for (int b = 0; b < 8; b++) { ar[b] = 0; az[b] = 0; an[b] = 0; }

        #pragma unroll
        for (int b = 0; b < 8; b++) {
            const float4* hb = (const float4*)(hsrc + b * Hsz + kc * 32);
            #pragma unroll
            for (int i = 0; i < 8; i++) {
                float4 hv = __ldcg(hb + i);
                ar[b] += wr[i].x*hv.x + wr[i].y*hv.y + wr[i].z*hv.z + wr[i].w*hv.w;
                az[b] += wz[i].x*hv.x + wz[i].y*hv.y + wz[i].z*hv.z + wz[i].w*hv.w;
                an[b] += wn[i].x*hv.x + wn[i].y*hv.y + wn[i].z*hv.z + wn[i].w*hv.w;
            }
        }

        // reduce over the 16 kc-lanes
        #pragma unroll
        for (int off = 1; off <= 8; off <<= 1) {
            #pragma unroll
            for (int b = 0; b < 8; b++) {
                ar[b] += __shfl_xor_sync(0xffffffffu, ar[b], off);
                az[b] += __shfl_xor_sync(0xffffffffu, az[b], off);
                an[b] += __shfl_xor_sync(0xffffffffu, an[b], off);
            }
        }

        const int w = (t + 1) & 1;
        if (owner) {
            #pragma unroll
            for (int b = 0; b < 8; b++) {
                float r = 1.0f / (1.0f + expf(-(gir[b] + ar[b] + bhr)));
                float z = 1.0f / (1.0f + expf(-(giz[b] + az[b] + bhz)));
                float n = tanhf(gin[b] + r * (an[b] + bhn));
                float hnew = (1.0f - z) * n + z * holdr[b];
                holdr[b] = hnew;
                out[(long)((b << 7) + t) * Hsz + j] = hnew;
                hglob[w * (Bsz * Hsz) + b * Hsz + j] = hnew;
            }
            if (t + 1 < Lsz) {
                #pragma unroll
                for (int b = 0; b < 8; b++) {
                    long g = (long)((b << 7) + t + 1) * (3 * Hsz);
                    gir[b] = __ldcg(&gi[g + j]);
                    giz[b] = __ldcg(&gi[g + Hsz + j]);
                    gin[b] = __ldcg(&gi[g + 2 * Hsz + j]);
                }
            }
        }
        if (t + 1 < Lsz) {
            __threadfence();
            __syncthreads();
            if (tid == 0) {
                unsigned epoch = (unsigned)(t + 1);
                unsigned old = atomicAdd(counter, 1u);
                if (old == epoch * GRU_BLOCKS - 1u) {
                    __threadfence();
                    *(volatile unsigned*)release = epoch;   // written ONCE per step
                }
                volatile unsigned* vr = release;
                while (*vr < epoch) { }
            }
            __syncthreads();
        }
    }
}

// ---------------- copy-attention context (alphas independent of i) -------
__global__ void copy_ctx_kernel(const float* __restrict__ enc_out,
                                const int* __restrict__ enc_in,
                                const float* __restrict__ copyW,
                                float* __restrict__ ctx) {
    __shared__ float4 we4[Hsz / 4];
    __shared__ float alpha[Lsz];
    __shared__ float rbuf[Lsz];
    int b = blockIdx.x, tid = threadIdx.x;
    we4[tid] = ((const float4*)copyW)[tid];
    __syncthreads();
    const float4* row = (const float4*)(enc_out + (long)(b * Lsz + tid) * Hsz);
    float s = 0.0f;
    for (int k = 0; k < Hsz / 4; k++) {
        float4 r = row[k], w = we4[k];
        s += r.x*w.x + r.y*w.y + r.z*w.z + r.w*w.w;
    }
    if (enc_in[b * Lsz + tid] == 0) s -= 1000.0f;
    rbuf[tid] = s; __syncthreads();
    for (int st = 64; st > 0; st >>= 1) {
        if (tid < st) rbuf[tid] = fmaxf(rbuf[tid], rbuf[tid + st]);
        __syncthreads();
    }
    float m = rbuf[0]; __syncthreads();
    float e = expf(s - m);
    rbuf[tid] = e; __syncthreads();
    for (int st = 64; st > 0; st >>= 1) {
        if (tid < st) rbuf[tid] += rbuf[tid + st];
        __syncthreads();
    }
    alpha[tid] = e / rbuf[0];
    __syncthreads();
    float a0 = 0, a1 = 0, a2 = 0, a3 = 0;
    const float* E = enc_out + (long)b * Lsz * Hsz;
    for (int jj = 0; jj < Lsz; jj++) {
        float a = alpha[jj];
        const float* er = E + jj * Hsz;
        a0 += a * er[tid];       a1 += a * er[tid + 128];
        a2 += a * er[tid + 256]; a3 += a * er[tid + 384];
    }
    float* o = ctx + (long)b * Hsz;
    o[tid] = a0; o[tid + 128] = a1; o[tid + 256] = a2; o[tid + 384] = a3;
}

// ---------------- mix gate ------------------------------------------------
__global__ void mix_kernel(const float* __restrict__ gruout,
                           const float* __restrict__ ctx,
                           const float* __restrict__ ea,
                           const float* __restrict__ dgW,
                           const float* __restrict__ dgb,
                           float* __restrict__ mixbuf) {
    int row = blockIdx.x;
    int b = row >> 7;
    int tid = threadIdx.x;
    const float* g = gruout + (long)row * Hsz;
    const float* c = ctx + (long)b * Hsz;
    const float* e = ea + (long)row * 1024;
    float s = 0.0f;
    for (int k = tid; k < Hsz; k += 128)
        s += g[k] * dgW[k] + c[k] * dgW[Hsz + k] + e[k] * dgW[2 * Hsz + k];
    __shared__ float rbuf[128];
    rbuf[tid] = s; __syncthreads();
    for (int st = 64; st > 0; st >>= 1) {
        if (tid < st) rbuf[tid] += rbuf[tid + st];
        __syncthreads();
    }
    if (tid == 0) mixbuf[row] = 1.0f / (1.0f + expf(-(rbuf[0] + dgb[0])));
}

// ---------------- final: online softmax over V (+out_b) + pointer mix ----
__global__ void softmax_mix_kernel(float* __restrict__ prob,
                                   const float* __restrict__ mixbuf,
                                   const int* __restrict__ enc_in,
                                   const float* __restrict__ ob) {
    int row = blockIdx.x;
    int tid = threadIdx.x;
    float* p = prob + (long)row * Vsz;
    const float4* ob4 = (const float4*)ob;
    float m = -1e30f, s = 0.0f;
    const float4* p4 = (const float4*)p;
    for (int v = tid; v < Vsz / 4; v += 256) {
        float4 x = p4[v];
        float4 bb = ob4[v];
        x.x += bb.x; x.y += bb.y; x.z += bb.z; x.w += bb.w;
        float lm = fmaxf(fmaxf(x.x, x.y), fmaxf(x.z, x.w));
        if (lm > m) { s *= expf(m - lm); m = lm; }
        s += expf(x.x - m) + expf(x.y - m) + expf(x.z - m) + expf(x.w - m);
    }
    __shared__ float rm[256], rs[256];
    rm[tid] = m; rs[tid] = s; __syncthreads();
    for (int st = 128; st > 0; st >>= 1) {
        if (tid < st) {
            float m2 = rm[tid + st], s2 = rs[tid + st];
            float M = fmaxf(rm[tid], m2);
            rs[tid] = rs[tid] * expf(rm[tid] - M) + s2 * expf(m2 - M);
            rm[tid] = M;
        }
        __syncthreads();
    }
    float M = rm[0], S = rs[0];
    float mix = mixbuf[row];
    float inv = mix / S;
    float add = 1.0f - mix;
    int tok = enc_in[row];
    float4* w4 = (float4*)p;
    for (int v = tid; v < Vsz / 4; v += 256) {
        float4 x = w4[v];
        float4 bb = ob4[v];
        x.x = expf(x.x + bb.x - M) * inv;
        x.y = expf(x.y + bb.y - M) * inv;
        x.z = expf(x.z + bb.z - M) * inv;
        x.w = expf(x.w + bb.w - M) * inv;
        int base = v * 4;
        if (tok >= base && tok < base + 4) {
            if (tok == base)     x.x += add;
            else if (tok == base + 1) x.y += add;
            else if (tok == base + 2) x.z += add;
            else                 x.w += add;
        }
        w4[v] = x;
    }
}

// ---------------- launch --------------------------------------------------
extern "C" void kernel_launch(void* const* d_in, const int* in_sizes, int n_in,
                              void* d_out, int out_size) {
    (void)in_sizes; (void)n_in; (void)out_size;
    const int*   input_   = (const int*)d_in[0];
    const int*   enc_in   = (const int*)d_in[1];
    const float* enc_hid  = (const float*)d_in[2];
    const float* enc_out  = (const float*)d_in[3];
    const float* emb_tab  = (const float*)d_in[4];
    const float* attn_W   = (const float*)d_in[5];
    const float* comb_W   = (const float*)d_in[7];
    const float* comb_b   = (const float*)d_in[8];
    const float* gru_Wih  = (const float*)d_in[9];
    const float* gru_Whh  = (const float*)d_in[10];
    const float* gru_bih  = (const float*)d_in[11];
    const float* gru_bhh  = (const float*)d_in[12];
    const float* out_W    = (const float*)d_in[13];
    const float* out_b    = (const float*)d_in[14];
    const float* dogen_W  = (const float*)d_in[15];
    const float* dogen_b  = (const float*)d_in[16];
    const float* copy_W   = (const float*)d_in[17];

    float* out   = (float*)d_out;
    float* prob  = out;
    float* attnw = out + PROB_ELEMS;

    float* sc = nullptr;
    cudaGetSymbolAddress((void**)&sc, d_scratch);
    float* ea      = sc + OFF_EA;
    float* sattn   = sc + OFF_SATTN;
    float* xbuf    = sc + OFF_X;
    float* gibuf   = sc + OFF_GI;
    float* gruout  = sc + OFF_GRUOUT;
    float* ctx     = sc + OFF_CTX;
    float* mixb    = sc + OFF_MIX;
    float* hglob   = sc + OFF_HGLOB;
    unsigned* bar  = (unsigned*)(sc + OFF_BAR);

    __nv_bfloat16 *Bhi = nullptr, *Blo = nullptr, *Ahi = nullptr, *Alo = nullptr;
    cudaGetSymbolAddress((void**)&Bhi, d_Bhi);
    cudaGetSymbolAddress((void**)&Blo, d_Blo);
    cudaGetSymbolAddress((void**)&Ahi, d_Ahi);
    cudaGetSymbolAddress((void**)&Alo, d_Alo);

    cudaFuncSetAttribute(mma_out_gemm, cudaFuncAttributeMaxDynamicSharedMemorySize, MMA_SMEM);

    // 1. embedding gather into EA[:, 0:512]
    gather_kernel<<<NROWS, 128>>>(input_, emb_tab, ea);
    // 1b. split out_W into bf16 hi/lo
    {
        int n4 = Vsz * Hsz / 4;
        split_bf16_kernel<<<(n4 + 255) / 256, 256>>>(out_W, Bhi, Blo, n4);
    }
    // 2. attn logits (emb part only; h0/attn_b cancel in axis=1 softmax)
    sgemm128_kernel<<<dim3(Lsz / BN, NROWS / BM), 256>>>(
        ea, 1024, attn_W, 2 * Hsz, sattn, Lsz, Hsz, nullptr, 0);
    // 3. softmax over i -> attn_weights (output tail)
    attn_softmax_kernel<<<Bsz, Lsz>>>(sattn, attnw);
    // 4. attn_applied into EA[:, 512:1024]
    attn_applied_kernel<<<NROWS, 128>>>(attnw, enc_out, ea);
    // 5. comb: x = relu(EA @ comb_W^T + b), single K=1024 GEMM
    sgemm128_kernel<<<dim3(Hsz / BN, NROWS / BM), 256>>>(
        ea, 1024, comb_W, 1024, xbuf, Hsz, 1024, comb_b, FLAG_BIAS | FLAG_RELU);
    // 6. gi = x @ Wih^T + bih
    sgemm128_kernel<<<dim3(3 * Hsz / BN, NROWS / BM), 256>>>(
        xbuf, Hsz, gru_Wih, Hsz, gibuf, 3 * Hsz, Hsz, gru_bih, FLAG_BIAS);
    // 7. GRU (register-weight persistent, release-flag barrier)
    reset_bar_kernel<<<1, 1>>>(bar);
    gru_kernel<<<GRU_BLOCKS, GRU_THREADS>>>(
        gru_Whh, gru_bhh, gibuf, enc_hid, gruout, hglob, bar);
    // 7b. split gruout into bf16 hi/lo
    {
        int n4 = NROWS * Hsz / 4;
        split_bf16_kernel<<<(n4 + 255) / 256, 256>>>(gruout, Ahi, Alo, n4);
    }
    // 8. output logits: WMMA split-bf16 GEMM straight into d_out
    mma_out_gemm<<<dim3(NROWS / 128, Vsz / 128), 256, MMA_SMEM>>>(
        Ahi, Alo, Bhi, Blo, prob);
    // 9. copy-attention context (alphas i-independent)
    copy_ctx_kernel<<<Bsz, Lsz>>>(enc_out, enc_in, copy_W, ctx);
    // 10. mix gate
    mix_kernel<<<NROWS, 128>>>(gruout, ctx, ea, dogen_W, dogen_b, mixb);
    // 11. online softmax over V (+out_b) + pointer mix, in place
    softmax_mix_kernel<<<NROWS, 256>>>(prob, mixb, enc_in, out_b);
}

// round 16
// speedup vs baseline: 1.2339x; 1.2339x over previous
#include <cuda_runtime.h>
#include <cuda_bf16.h>
#include <mma.h>
#include <math.h>

using namespace nvcuda;

// Problem dims
#define Bsz 8
#define Lsz 128
#define Hsz 512
#define Vsz 32000
#define NROWS (Bsz * Lsz)        // 1024
#define PROB_ELEMS ((long)NROWS * Vsz)   // 32768000

// ---------------- scratch (single __device__ global, offsets in floats) ---
// EA = [1024 rows][1024 cols]: cols 0-511 = embedded, cols 512-1023 = attn_applied
#define OFF_EA       0
#define OFF_SATTN    (OFF_EA + NROWS * 1024)
#define OFF_X        (OFF_SATTN + NROWS * Lsz)
#define OFF_GI       (OFF_X + NROWS * Hsz)
#define OFF_GRUOUT   (OFF_GI + NROWS * 3 * Hsz)
#define OFF_CTX      (OFF_GRUOUT + NROWS * Hsz)
#define OFF_MIX      (OFF_CTX + Bsz * Hsz)
#define OFF_HGLOB    (OFF_MIX + NROWS)
#define OFF_BAR      (OFF_HGLOB + 2 * Bsz * Hsz)
#define SCRATCH_TOTAL (OFF_BAR + 64)

__device__ float d_scratch[SCRATCH_TOTAL];

// bf16 buffers for the big GEMM (single-precision-term bf16 path)
__device__ __nv_bfloat16 d_Bw[(long)Vsz * Hsz];
__device__ __nv_bfloat16 d_Aw[NROWS * Hsz];

// ---------------- embedding gather (into EA cols 0-511) -------------------
__global__ void gather_kernel(const int* __restrict__ toks,
                              const float* __restrict__ emb,
                              float* __restrict__ ea) {
    int row = blockIdx.x;
    int tok = toks[row];
    const float4* s = (const float4*)(emb + (long)tok * Hsz);
    float4* d = (float4*)(ea + (long)row * 1024);
    d[threadIdx.x] = s[threadIdx.x];
}

// ---------------- fp32 -> bf16 convert ------------------------------------
__global__ void tobf16_kernel(const float* __restrict__ src,
                              __nv_bfloat16* __restrict__ dst, int n4) {
    int i = blockIdx.x * blockDim.x + threadIdx.x;
    if (i >= n4) return;
    float4 x = ((const float4*)src)[i];
    __nv_bfloat162 a, b;
    a.x = __float2bfloat16(x.x); a.y = __float2bfloat16(x.y);
    b.x = __float2bfloat16(x.z); b.y = __float2bfloat16(x.w);
    ((__nv_bfloat162*)dst)[2 * i]     = a;
    ((__nv_bfloat162*)dst)[2 * i + 1] = b;
}

// ---------------- plain bf16 WMMA GEMM ------------------------------------
// C[1024][32000] = A[M][512] * B[N][512]^T   (bias folded into softmax)
// Block 128x128, BK=32, 8 warps (2m x 4n), warp tile 64x32 = 4x2 wmma tiles.
#define TSTRIDE 40   // bf16 per smem row: 32 data + 8 pad (80 B, mult of 16 B)
#define MMA_SMEM (2 * 2 * 128 * TSTRIDE * 2)   // 40960 bytes

__global__ __launch_bounds__(256)
void mma_out_gemm(const __nv_bfloat16* __restrict__ gA,
                  const __nv_bfloat16* __restrict__ gB,
                  float* __restrict__ C) {
    extern __shared__ __nv_bfloat16 smb[];
    const int SEG = 128 * TSTRIDE;           // 5120 bf16 per array
    const int tid = threadIdx.x;
    const int warp = tid >> 5;
    const long bm = (long)blockIdx.x * 128;  // 8 m-blocks
    const long bn = (long)blockIdx.y * 128;  // 250 n-blocks
    const int wm = (warp & 1) * 64;
    const int wn = (warp >> 1) * 32;

    wmma::fragment<wmma::accumulator, 16, 16, 16, float> acc[4][2];
    #pragma unroll
    for (int mi = 0; mi < 4; mi++)
        #pragma unroll
        for (int ni = 0; ni < 2; ni++)
            wmma::fill_fragment(acc[mi][ni], 0.0f);

    // global->smem: 512 16B-chunks per array-tile; each thread moves 2
    const int r0 = tid >> 2, k80 = (tid & 3) * 8;
    const int r1 = (tid + 256) >> 2, k81 = ((tid + 256) & 3) * 8;

    const __nv_bfloat16* gsrc[2];
    gsrc[0] = gA + bm * Hsz;
    gsrc[1] = gB + bn * Hsz;

    uint4 pf[2][2];
    const int NT = Hsz / 32;   // 16

    #pragma unroll
    for (int a = 0; a < 2; a++) {
        pf[a][0] = *(const uint4*)(gsrc[a] + (long)r0 * Hsz + k80);
        pf[a][1] = *(const uint4*)(gsrc[a] + (long)r1 * Hsz + k81);
    }
    #pragma unroll
    for (int a = 0; a < 2; a++) {
        *(uint4*)(smb + a * SEG + r0 * TSTRIDE + k80) = pf[a][0];
        *(uint4*)(smb + a * SEG + r1 * TSTRIDE + k81) = pf[a][1];
    }
    __syncthreads();

    for (int t = 0; t < NT; t++) {
        const int buf = t & 1;
        const bool more = (t + 1 < NT);
        if (more) {
            const int kt = (t + 1) * 32;
            #pragma unroll
            for (int a = 0; a < 2; a++) {
                pf[a][0] = *(const uint4*)(gsrc[a] + (long)r0 * Hsz + kt + k80);
                pf[a][1] = *(const uint4*)(gsrc[a] + (long)r1 * Hsz + kt + k81);
            }
        }

        const __nv_bfloat16* sA = smb + buf * 2 * SEG + 0 * SEG;
        const __nv_bfloat16* sB = smb + buf * 2 * SEG + 1 * SEG;

        #pragma unroll
        for (int ks = 0; ks < 32; ks += 16) {
            wmma::fragment<wmma::matrix_b, 16, 16, 16, __nv_bfloat16, wmma::col_major> fb[2];
            #pragma unroll
            for (int ni = 0; ni < 2; ni++)
                wmma::load_matrix_sync(fb[ni], sB + (wn + ni * 16) * TSTRIDE + ks, TSTRIDE);
            #pragma unroll
            for (int mi = 0; mi < 4; mi++) {
                wmma::fragment<wmma::matrix_a, 16, 16, 16, __nv_bfloat16, wmma::row_major> fa;
                wmma::load_matrix_sync(fa, sA + (wm + mi * 16) * TSTRIDE + ks, TSTRIDE);
                #pragma unroll
                for (int ni = 0; ni < 2; ni++)
                    wmma::mma_sync(acc[mi][ni], fa, fb[ni], acc[mi][ni]);
            }
        }

        if (more) {
            const int nb = buf ^ 1;
            #pragma unroll
            for (int a = 0; a < 2; a++) {
                *(uint4*)(smb + nb * 2 * SEG + a * SEG + r0 * TSTRIDE + k80) = pf[a][0];
                *(uint4*)(smb + nb * 2 * SEG + a * SEG + r1 * TSTRIDE + k81) = pf[a][1];
            }
        }
        __syncthreads();
    }

    #pragma unroll
    for (int mi = 0; mi < 4; mi++)
        #pragma unroll
        for (int ni = 0; ni < 2; ni++) {
            long m = bm + wm + mi * 16;
            long n = bn + wn + ni * 16;
            wmma::store_matrix_sync(C + m * Vsz + n, acc[mi][ni], Vsz, wmma::mem_row_major);
        }
}

// ---------------- SGEMM 128x128x16 for the small GEMMs --------------------
#define FLAG_ACCUM 1
#define FLAG_BIAS  2
#define FLAG_RELU  4
#define BM 128
#define BN 128
#define BK 16
#define SPAD 4

__global__ __launch_bounds__(256)
void sgemm128_kernel(const float* __restrict__ A, int lda,
                     const float* __restrict__ B, int ldb,
                     float* __restrict__ C, int ldc,
                     int K, const float* __restrict__ bias, int flags) {
    __shared__ float As[2][BK][BM + SPAD];
    __shared__ float Bs[2][BK][BN + SPAD];

    const int tid = threadIdx.x;
    const int tx = tid & 15;
    const int ty = tid >> 4;
    const long bm = (long)blockIdx.y * BM;
    const long bn = (long)blockIdx.x * BN;

    const int r0 = tid >> 2;
    const int r1 = r0 + 64;
    const int kq = (tid & 3) << 2;

    const float* Ag = A + (bm + r0) * lda + kq;
    const float* Ag2 = A + (bm + r1) * lda + kq;
    const float* Bg = B + (bn + r0) * ldb + kq;
    const float* Bg2 = B + (bn + r1) * ldb + kq;

    float acc[8][8];
    #pragma unroll
    for (int i = 0; i < 8; i++)
        #pragma unroll
        for (int j = 0; j < 8; j++) acc[i][j] = 0.0f;

    {
        float4 a0 = *(const float4*)(Ag);
        float4 a1 = *(const float4*)(Ag2);
        float4 b0 = *(const float4*)(Bg);
        float4 b1 = *(const float4*)(Bg2);
        As[0][kq + 0][r0] = a0.x; As[0][kq + 1][r0] = a0.y;
        As[0][kq + 2][r0] = a0.z; As[0][kq + 3][r0] = a0.w;
        As[0][kq + 0][r1] = a1.x; As[0][kq + 1][r1] = a1.y;
        As[0][kq + 2][r1] = a1.z; As[0][kq + 3][r1] = a1.w;
        Bs[0][kq + 0][r0] = b0.x; Bs[0][kq + 1][r0] = b0.y;
        Bs[0][kq + 2][r0] = b0.z; Bs[0][kq + 3][r0] = b0.w;
        Bs[0][kq + 0][r1] = b1.x; Bs[0][kq + 1][r1] = b1.y;
        Bs[0][kq + 2][r1] = b1.z; Bs[0][kq + 3][r1] = b1.w;
    }
    __syncthreads();

    int buf = 0;
    const int T = K / BK;
    for (int t = 0; t < T; t++) {
        float4 a0, a1, b0, b1;
        const bool more = (t + 1 < T);
        if (more) {
            int kt = (t + 1) * BK;
            a0 = *(const float4*)(Ag + kt);
            a1 = *(const float4*)(Ag2 + kt);
            b0 = *(const float4*)(Bg + kt);
            b1 = *(const float4*)(Bg2 + kt);
        }
        #pragma unroll
        for (int k = 0; k < BK; k++) {
            float4 af0 = *(const float4*)&As[buf][k][ty * 8];
            float4 af1 = *(const float4*)&As[buf][k][ty * 8 + 4];
            float4 bf0 = *(const float4*)&Bs[buf][k][tx * 8];
            float4 bf1 = *(const float4*)&Bs[buf][k][tx * 8 + 4];
            float ar[8] = {af0.x, af0.y, af0.z, af0.w, af1.x, af1.y, af1.z, af1.w};
            float br[8] = {bf0.x, bf0.y, bf0.z, bf0.w, bf1.x, bf1.y, bf1.z, bf1.w};
            #pragma unroll
            for (int i = 0; i < 8; i++)
                #pragma unroll
                for (int j = 0; j < 8; j++)
                    acc[i][j] += ar[i] * br[j];
        }
        if (more) {
            int nb = buf ^ 1;
            As[nb][kq + 0][r0] = a0.x; As[nb][kq + 1][r0] = a0.y;
            As[nb][kq + 2][r0] = a0.z; As[nb][kq + 3][r0] = a0.w;
            As[nb][kq + 0][r1] = a1.x; As[nb][kq + 1][r1] = a1.y;
            As[nb][kq + 2][r1] = a1.z; As[nb][kq + 3][r1] = a1.w;
            Bs[nb][kq + 0][r0] = b0.x; Bs[nb][kq + 1][r0] = b0.y;
            Bs[nb][kq + 2][r0] = b0.z; Bs[nb][kq + 3][r0] = b0.w;
            Bs[nb][kq + 0][r1] = b1.x; Bs[nb][kq + 1][r1] = b1.y;
            Bs[nb][kq + 2][r1] = b1.z; Bs[nb][kq + 3][r1] = b1.w;
        }
        __syncthreads();
        buf ^= 1;
    }

    #pragma unroll
    for (int i = 0; i < 8; i++) {
        long m = bm + ty * 8 + i;
        long n = bn + tx * 8;
        float* cp = C + m * ldc + n;
        float v[8];
        #pragma unroll
        for (int j = 0; j < 8; j++) v[j] = acc[i][j];
        if (flags & FLAG_ACCUM) {
            float4 cc0 = *(float4*)(cp);
            float4 cc1 = *(float4*)(cp + 4);
            v[0]+=cc0.x; v[1]+=cc0.y; v[2]+=cc0.z; v[3]+=cc0.w;
            v[4]+=cc1.x; v[5]+=cc1.y; v[6]+=cc1.z; v[7]+=cc1.w;
        }
        if (flags & FLAG_BIAS) {
            float4 bb0 = *(const float4*)(bias + n);
            float4 bb1 = *(const float4*)(bias + n + 4);
            v[0]+=bb0.x; v[1]+=bb0.y; v[2]+=bb0.z; v[3]+=bb0.w;
            v[4]+=bb1.x; v[5]+=bb1.y; v[6]+=bb1.z; v[7]+=bb1.w;
        }
        if (flags & FLAG_RELU) {
            #pragma unroll
            for (int j = 0; j < 8; j++) v[j] = fmaxf(v[j], 0.0f);
        }
        *(float4*)(cp)     = make_float4(v[0], v[1], v[2], v[3]);
        *(float4*)(cp + 4) = make_float4(v[4], v[5], v[6], v[7]);
    }
}

// ---------------- attention softmax over axis=1 (over i, per (b,j)) ------
__global__ void attn_softmax_kernel(const float* __restrict__ S,
                                    float* __restrict__ W) {
    int b = blockIdx.x;
    int j = threadIdx.x;
    const float* p = S + (long)b * Lsz * Lsz + j;
    float m = -1e30f;
    for (int i = 0; i < Lsz; i++) m = fmaxf(m, p[i * Lsz]);
    float s = 0.0f;
    for (int i = 0; i < Lsz; i++) s += expf(p[i * Lsz] - m);
    float inv = 1.0f / s;
    float* w = W + (long)b * Lsz * Lsz + j;
    for (int i = 0; i < Lsz; i++) w[i * Lsz] = expf(p[i * Lsz] - m) * inv;
}

// ---------------- attn_applied -> EA cols 512-1023 ------------------------
__global__ void attn_applied_kernel(const float* __restrict__ attnw,
                                    const float* __restrict__ enc_out,
                                    float* __restrict__ ea) {
    int row = blockIdx.x;
    int b = row >> 7;
    __shared__ float w[Lsz];
    int tid = threadIdx.x;
    w[tid] = attnw[(long)row * Lsz + tid];
    __syncthreads();
    float a0 = 0, a1 = 0, a2 = 0, a3 = 0;
    const float* E = enc_out + (long)b * Lsz * Hsz;
    for (int j = 0; j < Lsz; j++) {
        float a = w[j];
        const float* er = E + j * Hsz;
        a0 += a * er[tid];       a1 += a * er[tid + 128];
        a2 += a * er[tid + 256]; a3 += a * er[tid + 384];
    }
    float* o = ea + (long)row * 1024 + 512;
    o[tid] = a0; o[tid + 128] = a1; o[tid + 256] = a2; o[tid + 384] = a3;
}

// ---------------- GRU: register-weight persistent kernel (R13 barrier) ----
#define GRU_BLOCKS 64
#define GRU_THREADS 128

__global__ void reset_bar_kernel(unsigned* bar) { bar[0] = 0u; }

__global__ void gru_kernel(const float* __restrict__ Whh,
                           const float* __restrict__ bhh,
                           const float* __restrict__ gi,
                           const float* __restrict__ h0,
                           float* __restrict__ out,
                           float* __restrict__ hglob,
                           unsigned* __restrict__ bar) {
    const int blk = blockIdx.x;
    const int tid = threadIdx.x;
    const int kc = tid & 15;
    const int jl = tid >> 4;
    const int j = (blk << 3) + jl;
    const bool owner = (kc == 0);

    // load weights into registers (96 floats)
    float4 wr[8], wz[8], wn[8];
    {
        const float4* Wr = (const float4*)(Whh + (long)j * Hsz + kc * 32);
        const float4* Wz = (const float4*)(Whh + (long)(Hsz + j) * Hsz + kc * 32);
        const float4* Wn = (const float4*)(Whh + (long)(2 * Hsz + j) * Hsz + kc * 32);
        #pragma unroll
        for (int i = 0; i < 8; i++) { wr[i] = Wr[i]; wz[i] = Wz[i]; wn[i] = Wn[i]; }
    }

    float bhr = 0, bhz = 0, bhn = 0;
    float holdr[8];
    float gir[8], giz[8], gin[8];
    if (owner) {
        bhr = bhh[j]; bhz = bhh[Hsz + j]; bhn = bhh[2 * Hsz + j];
        #pragma unroll
        for (int b = 0; b < 8; b++) {
            holdr[b] = h0[b * Hsz + j];
            long g = (long)(b << 7) * (3 * Hsz);   // t = 0
            gir[b] = gi[g + j];
            giz[b] = gi[g + Hsz + j];
            gin[b] = gi[g + 2 * Hsz + j];
        }
    }

    unsigned target = 0;

    for (int t = 0; t < Lsz; t++) {
        const float* hsrc = (t == 0) ? h0 : (hglob + (t & 1) * (Bsz * Hsz));
        float ar[8], az[8], an[8];
        #pragma unroll
        for (int b = 0; b < 8; b++) { ar[b] = 0; az[b] = 0; an[b] = 0; }

        #pragma unroll
        for (int b = 0; b < 8; b++) {
            const float4* hb = (const float4*)(hsrc + b * Hsz + kc * 32);
            #pragma unroll
            for (int i = 0; i < 8; i++) {
                float4 hv = __ldcg(hb + i);
                ar[b] += wr[i].x*hv.x + wr[i].y*hv.y + wr[i].z*hv.z + wr[i].w*hv.w;
                az[b] += wz[i].x*hv.x + wz[i].y*hv.y + wz[i].z*hv.z + wz[i].w*hv.w;
                an[b] += wn[i].x*hv.x + wn[i].y*hv.y + wn[i].z*hv.z + wn[i].w*hv.w;
            }
        }

        // reduce over the 16 kc-lanes
        #pragma unroll
        for (int off = 1; off <= 8; off <<= 1) {
            #pragma unroll
            for (int b = 0; b < 8; b++) {
                ar[b] += __shfl_xor_sync(0xffffffffu, ar[b], off);
                az[b] += __shfl_xor_sync(0xffffffffu, az[b], off);
                an[b] += __shfl_xor_sync(0xffffffffu, an[b], off);
            }
        }

        const int w = (t + 1) & 1;
        if (owner) {
            #pragma unroll
            for (int b = 0; b < 8; b++) {
                float r = 1.0f / (1.0f + expf(-(gir[b] + ar[b] + bhr)));
                float z = 1.0f / (1.0f + expf(-(giz[b] + az[b] + bhz)));
                float n = tanhf(gin[b] + r * (an[b] + bhn));
                float hnew = (1.0f - z) * n + z * holdr[b];
                holdr[b] = hnew;
                out[(long)((b << 7) + t) * Hsz + j] = hnew;
                hglob[w * (Bsz * Hsz) + b * Hsz + j] = hnew;
            }
            if (t + 1 < Lsz) {
                #pragma unroll
                for (int b = 0; b < 8; b++) {
                    long g = (long)((b << 7) + t + 1) * (3 * Hsz);
                    gir[b] = __ldcg(&gi[g + j]);
                    giz[b] = __ldcg(&gi[g + Hsz + j]);
                    gin[b] = __ldcg(&gi[g + 2 * Hsz + j]);
                }
            }
        }
        if (t + 1 < Lsz) {
            __threadfence();
            __syncthreads();
            if (tid == 0) {
                atomicAdd(bar, 1u);
                target += GRU_BLOCKS;
                volatile unsigned* vb = bar;
                while (*vb < target) { }
            }
            __syncthreads();
        }
    }
}

// ---------------- copy-attention context (alphas independent of i) -------
__global__ void copy_ctx_kernel(const float* __restrict__ enc_out,
                                const int* __restrict__ enc_in,
                                const float* __restrict__ copyW,
                                float* __restrict__ ctx) {
    __shared__ float4 we4[Hsz / 4];
    __shared__ float alpha[Lsz];
    __shared__ float rbuf[Lsz];
    int b = blockIdx.x, tid = threadIdx.x;
    we4[tid] = ((const float4*)copyW)[tid];
    __syncthreads();
    const float4* row = (const float4*)(enc_out + (long)(b * Lsz + tid) * Hsz);
    float s = 0.0f;
    for (int k = 0; k < Hsz / 4; k++) {
        float4 r = row[k], w = we4[k];
        s += r.x*w.x + r.y*w.y + r.z*w.z + r.w*w.w;
    }
    if (enc_in[b * Lsz + tid] == 0) s -= 1000.0f;
    rbuf[tid] = s; __syncthreads();
    for (int st = 64; st > 0; st >>= 1) {
        if (tid < st) rbuf[tid] = fmaxf(rbuf[tid], rbuf[tid + st]);
        __syncthreads();
    }
    float m = rbuf[0]; __syncthreads();
    float e = expf(s - m);
    rbuf[tid] = e; __syncthreads();
    for (int st = 64; st > 0; st >>= 1) {
        if (tid < st) rbuf[tid] += rbuf[tid + st];
        __syncthreads();
    }
    alpha[tid] = e / rbuf[0];
    __syncthreads();
    float a0 = 0, a1 = 0, a2 = 0, a3 = 0;
    const float* E = enc_out + (long)b * Lsz * Hsz;
    for (int jj = 0; jj < Lsz; jj++) {
        float a = alpha[jj];
        const float* er = E + jj * Hsz;
        a0 += a * er[tid];       a1 += a * er[tid + 128];
        a2 += a * er[tid + 256]; a3 += a * er[tid + 384];
    }
    float* o = ctx + (long)b * Hsz;
    o[tid] = a0; o[tid + 128] = a1; o[tid + 256] = a2; o[tid + 384] = a3;
}

// ---------------- mix gate ------------------------------------------------
__global__ void mix_kernel(const float* __restrict__ gruout,
                           const float* __restrict__ ctx,
                           const float* __restrict__ ea,
                           const float* __restrict__ dgW,
                           const float* __restrict__ dgb,
                           float* __restrict__ mixbuf) {
    int row = blockIdx.x;
    int b = row >> 7;
    int tid = threadIdx.x;
    const float* g = gruout + (long)row * Hsz;
    const float* c = ctx + (long)b * Hsz;
    const float* e = ea + (long)row * 1024;
    float s = 0.0f;
    for (int k = tid; k < Hsz; k += 128)
        s += g[k] * dgW[k] + c[k] * dgW[Hsz + k] + e[k] * dgW[2 * Hsz + k];
    __shared__ float rbuf[128];
    rbuf[tid] = s; __syncthreads();
    for (int st = 64; st > 0; st >>= 1) {
        if (tid < st) rbuf[tid] += rbuf[tid + st];
        __syncthreads();
    }
    if (tid == 0) mixbuf[row] = 1.0f / (1.0f + expf(-(rbuf[0] + dgb[0])));
}

// ---------------- final: online softmax over V (+out_b) + pointer mix ----
__global__ void softmax_mix_kernel(float* __restrict__ prob,
                                   const float* __restrict__ mixbuf,
                                   const int* __restrict__ enc_in,
                                   const float* __restrict__ ob) {
    int row = blockIdx.x;
    int tid = threadIdx.x;
    float* p = prob + (long)row * Vsz;
    const float4* ob4 = (const float4*)ob;
    float m = -1e30f, s = 0.0f;
    const float4* p4 = (const float4*)p;
    for (int v = tid; v < Vsz / 4; v += 256) {
        float4 x = p4[v];
        float4 bb = ob4[v];
        x.x += bb.x; x.y += bb.y; x.z += bb.z; x.w += bb.w;
        float lm = fmaxf(fmaxf(x.x, x.y), fmaxf(x.z, x.w));
        if (lm > m) { s *= expf(m - lm); m = lm; }
        s += expf(x.x - m) + expf(x.y - m) + expf(x.z - m) + expf(x.w - m);
    }
    __shared__ float rm[256], rs[256];
    rm[tid] = m; rs[tid] = s; __syncthreads();
    for (int st = 128; st > 0; st >>= 1) {
        if (tid < st) {
            float m2 = rm[tid + st], s2 = rs[tid + st];
            float M = fmaxf(rm[tid], m2);
            rs[tid] = rs[tid] * expf(rm[tid] - M) + s2 * expf(m2 - M);
            rm[tid] = M;
        }
        __syncthreads();
    }
    float M = rm[0], S = rs[0];
    float mix = mixbuf[row];
    float inv = mix / S;
    float add = 1.0f - mix;
    int tok = enc_in[row];
    float4* w4 = (float4*)p;
    for (int v = tid; v < Vsz / 4; v += 256) {
        float4 x = w4[v];
        float4 bb = ob4[v];
        x.x = expf(x.x + bb.x - M) * inv;
        x.y = expf(x.y + bb.y - M) * inv;
        x.z = expf(x.z + bb.z - M) * inv;
        x.w = expf(x.w + bb.w - M) * inv;
        int base = v * 4;
        if (tok >= base && tok < base + 4) {
            if (tok == base)     x.x += add;
            else if (tok == base + 1) x.y += add;
            else if (tok == base + 2) x.z += add;
            else                 x.w += add;
        }
        w4[v] = x;
    }
}

// ---------------- launch --------------------------------------------------
extern "C" void kernel_launch(void* const* d_in, const int* in_sizes, int n_in,
                              void* d_out, int out_size) {
    (void)in_sizes; (void)n_in; (void)out_size;
    const int*   input_   = (const int*)d_in[0];
    const int*   enc_in   = (const int*)d_in[1];
    const float* enc_hid  = (const float*)d_in[2];
    const float* enc_out  = (const float*)d_in[3];
    const float* emb_tab  = (const float*)d_in[4];
    const float* attn_W   = (const float*)d_in[5];
    const float* comb_W   = (const float*)d_in[7];
    const float* comb_b   = (const float*)d_in[8];
    const float* gru_Wih  = (const float*)d_in[9];
    const float* gru_Whh  = (const float*)d_in[10];
    const float* gru_bih  = (const float*)d_in[11];
    const float* gru_bhh  = (const float*)d_in[12];
    const float* out_W    = (const float*)d_in[13];
    const float* out_b    = (const float*)d_in[14];
    const float* dogen_W  = (const float*)d_in[15];
    const float* dogen_b  = (const float*)d_in[16];
    const float* copy_W   = (const float*)d_in[17];

    float* out   = (float*)d_out;
    float* prob  = out;
    float* attnw = out + PROB_ELEMS;

    float* sc = nullptr;
    cudaGetSymbolAddress((void**)&sc, d_scratch);
    float* ea      = sc + OFF_EA;
    float* sattn   = sc + OFF_SATTN;
    float* xbuf    = sc + OFF_X;
    float* gibuf   = sc + OFF_GI;
    float* gruout  = sc + OFF_GRUOUT;
    float* ctx     = sc + OFF_CTX;
    float* mixb    = sc + OFF_MIX;
    float* hglob   = sc + OFF_HGLOB;
    unsigned* bar  = (unsigned*)(sc + OFF_BAR);

    __nv_bfloat16 *Bw = nullptr, *Aw = nullptr;
    cudaGetSymbolAddress((void**)&Bw, d_Bw);
    cudaGetSymbolAddress((void**)&Aw, d_Aw);

    cudaFuncSetAttribute(mma_out_gemm, cudaFuncAttributeMaxDynamicSharedMemorySize, MMA_SMEM);

    // 1. embedding gather into EA[:, 0:512]
    gather_kernel<<<NROWS, 128>>>(input_, emb_tab, ea);
    // 1b. convert out_W -> bf16
    {
        int n4 = Vsz * Hsz / 4;
        tobf16_kernel<<<(n4 + 255) / 256, 256>>>(out_W, Bw, n4);
    }
    // 2. attn logits (emb part only; h0/attn_b cancel in axis=1 softmax)
    sgemm128_kernel<<<dim3(Lsz / BN, NROWS / BM), 256>>>(
        ea, 1024, attn_W, 2 * Hsz, sattn, Lsz, Hsz, nullptr, 0);
    // 3. softmax over i -> attn_weights (output tail)
    attn_softmax_kernel<<<Bsz, Lsz>>>(sattn, attnw);
    // 4. attn_applied into EA[:, 512:1024]
    attn_applied_kernel<<<NROWS, 128>>>(attnw, enc_out, ea);
    // 5. comb: x = relu(EA @ comb_W^T + b), single K=1024 GEMM
    sgemm128_kernel<<<dim3(Hsz / BN, NROWS / BM), 256>>>(
        ea, 1024, comb_W, 1024, xbuf, Hsz, 1024, comb_b, FLAG_BIAS | FLAG_RELU);
    // 6. gi = x @ Wih^T + bih
    sgemm128_kernel<<<dim3(3 * Hsz / BN, NROWS / BM), 256>>>(
        xbuf, Hsz, gru_Wih, Hsz, gibuf, 3 * Hsz, Hsz, gru_bih, FLAG_BIAS);
    // 7. GRU (register-weight persistent, counter-spin barrier)
    reset_bar_kernel<<<1, 1>>>(bar);
    gru_kernel<<<GRU_BLOCKS, GRU_THREADS>>>(
        gru_Whh, gru_bhh, gibuf, enc_hid, gruout, hglob, bar);
    // 7b. convert gruout -> bf16
    {
        int n4 = NROWS * Hsz / 4;
        tobf16_kernel<<<(n4 + 255) / 256, 256>>>(gruout, Aw, n4);
    }
    // 8. output logits: plain bf16 WMMA GEMM straight into d_out
    mma_out_gemm<<<dim3(NROWS / 128, Vsz / 128), 256, MMA_SMEM>>>(Aw, Bw, prob);
    // 9. copy-attention context (alphas i-independent)
    copy_ctx_kernel<<<Bsz, Lsz>>>(enc_out, enc_in, copy_W, ctx);
    // 10. mix gate
    mix_kernel<<<NROWS, 128>>>(gruout, ctx, ea, dogen_W, dogen_b, mixb);
    // 11. online softmax over V (+out_b) + pointer mix, in place
    softmax_mix_kernel<<<NROWS, 256>>>(prob, mixb, enc_in, out_b);
}